// round 1
// baseline (speedup 1.0000x reference)
#include <cuda_runtime.h>

#define BATCH 2
#define NN 512
#define DD 128
#define HH 256
#define KSLAB 32

// Scratch for precomputed first-layer split activations.
__device__ float g_hA[BATCH * NN * HH];
__device__ float g_hB[BATCH * NN * HH];

// ---------------------------------------------------------------------------
// Kernel 1: hA[b,n,h] = b1[h] + sum_d PhiA[b,n,d] * W1[d][h]
//           hB[b,n,h] =          sum_d PhiB[b,n,d] * W1[D+d][h]
// One block per (b,n) row, 256 threads (one per h).
// ---------------------------------------------------------------------------
__global__ __launch_bounds__(HH) void precompute_kernel(
    const float* __restrict__ PhiA, const float* __restrict__ PhiB,
    const float* __restrict__ W1, const float* __restrict__ b1) {
    int bn = blockIdx.x;      // [0, B*N)
    int h = threadIdx.x;      // [0, 256)
    __shared__ float sA[DD], sB[DD];
    if (h < DD) sA[h] = PhiA[bn * DD + h];
    else        sB[h - DD] = PhiB[bn * DD + (h - DD)];
    __syncthreads();
    float accA = b1[h];
    float accB = 0.0f;
#pragma unroll 8
    for (int d = 0; d < DD; d++) {
        accA = fmaf(sA[d], W1[d * HH + h], accA);
        accB = fmaf(sB[d], W1[(DD + d) * HH + h], accB);
    }
    g_hA[bn * HH + h] = accA;
    g_hB[bn * HH + h] = accB;
}

// ---------------------------------------------------------------------------
// Kernel 2: per block: 8 A-rows x 8 B-rows = 64 pairs.
//   H1s[k][p] = relu(hA[n0+p/8][k] + hB[m0+p%8][k])        (shared, 64KB)
//   acc[64 pairs][256 cols] = H1 @ W2 + b2  (register-blocked 8x8 per thread)
//   out[pair] = b3 + sum_col relu(acc) * W3[col]           (shuffle reduce)
// 256 threads: tp = t/32 selects pair group, tc = t%32 selects col group.
// Thread owns pairs {tp*4..+3, 32+tp*4..+3}, cols {tc*4..+3, 128+tc*4..+3}.
// ---------------------------------------------------------------------------
extern __shared__ float smem[];

__global__ __launch_bounds__(256, 1) void pair_mlp_kernel(
    const float* __restrict__ W2, const float* __restrict__ b2,
    const float* __restrict__ W3, const float* __restrict__ b3,
    float* __restrict__ out) {
    const int b  = blockIdx.z;
    const int n0 = blockIdx.y * 8;
    const int m0 = blockIdx.x * 8;

    float* H1s = smem;                   // 256*64   = 16384 floats
    float* W2s = smem + 16384;           // 32*256   =  8192 floats
    float* hAs = smem + 16384 + 8192;    // 8*257    =  2056 floats (padded)
    float* hBs = hAs + 8 * 257;          // 8*257

    const int t = threadIdx.x;

    // ---- stage hA / hB tiles (coalesced) ----
#pragma unroll
    for (int j = 0; j < 8; j++) {
        int i = t + j * 256;             // [0, 2048)
        int r = i >> 8;                  // row 0..7
        int k = i & 255;                 // col 0..255
        hAs[r * 257 + k] = g_hA[(b * NN + n0 + r) * HH + k];
        hBs[r * 257 + k] = g_hB[(b * NN + m0 + r) * HH + k];
    }
    __syncthreads();

    // ---- build H1s[k][p] = relu(hA[pa][k] + hB[pb][k]) ----
#pragma unroll 8
    for (int j = 0; j < 64; j++) {
        int i = t + j * 256;             // [0, 16384)
        int k = i >> 6;
        int p = i & 63;
        float v = hAs[(p >> 3) * 257 + k] + hBs[(p & 7) * 257 + k];
        H1s[i] = fmaxf(v, 0.0f);
    }
    // (H1s writes are fenced by the first __syncthreads in the slab loop)

    const int tp = t >> 5;               // 0..7  (constant per warp)
    const int tc = t & 31;               // 0..31 (lane)

    // accumulators: [pair-half][col-half][pair 0..3][col 0..3]
    float acc[2][2][4][4];
    {
        const float4* b2v = (const float4*)b2;
        float4 bc0 = b2v[tc];            // cols tc*4..+3
        float4 bc1 = b2v[tc + 32];       // cols 128+tc*4..+3
#pragma unroll
        for (int ih = 0; ih < 2; ih++)
#pragma unroll
            for (int i = 0; i < 4; i++) {
                acc[ih][0][i][0] = bc0.x; acc[ih][0][i][1] = bc0.y;
                acc[ih][0][i][2] = bc0.z; acc[ih][0][i][3] = bc0.w;
                acc[ih][1][i][0] = bc1.x; acc[ih][1][i][1] = bc1.y;
                acc[ih][1][i][2] = bc1.z; acc[ih][1][i][3] = bc1.w;
            }
    }

    // ---- main loop over K = 256 in slabs of 32 ----
    for (int ks = 0; ks < HH; ks += KSLAB) {
        __syncthreads();   // guards W2s reuse + (first iter) H1s completion
        {
            const float4* W2g = (const float4*)(W2 + ks * HH);
            float4* W2s4 = (float4*)W2s;
#pragma unroll
            for (int j = 0; j < 8; j++) W2s4[t + j * 256] = W2g[t + j * 256];
        }
        __syncthreads();

#pragma unroll 8
        for (int k = 0; k < KSLAB; k++) {
            const float4* h1row = (const float4*)(H1s + (ks + k) * 64);
            float4 a0 = h1row[tp];        // pairs tp*4..+3      (broadcast)
            float4 a1 = h1row[tp + 8];    // pairs 32+tp*4..+3
            const float4* w2row = (const float4*)(W2s + k * HH);
            float4 c0 = w2row[tc];        // cols tc*4..+3       (no conflict)
            float4 c1 = w2row[tc + 32];   // cols 128+tc*4..+3

            float av[2][4] = {{a0.x, a0.y, a0.z, a0.w}, {a1.x, a1.y, a1.z, a1.w}};
            float cv[2][4] = {{c0.x, c0.y, c0.z, c0.w}, {c1.x, c1.y, c1.z, c1.w}};
#pragma unroll
            for (int ih = 0; ih < 2; ih++)
#pragma unroll
                for (int jh = 0; jh < 2; jh++)
#pragma unroll
                    for (int i = 0; i < 4; i++)
#pragma unroll
                        for (int j = 0; j < 4; j++)
                            acc[ih][jh][i][j] = fmaf(av[ih][i], cv[jh][j],
                                                     acc[ih][jh][i][j]);
        }
    }

    // ---- epilogue: relu, dot with W3, reduce over col lanes ----
    float w3v[2][4];
    {
        const float4* W3v = (const float4*)W3;
        float4 w0 = W3v[tc];
        float4 w1 = W3v[tc + 32];
        w3v[0][0] = w0.x; w3v[0][1] = w0.y; w3v[0][2] = w0.z; w3v[0][3] = w0.w;
        w3v[1][0] = w1.x; w3v[1][1] = w1.y; w3v[1][2] = w1.z; w3v[1][3] = w1.w;
    }

    float psum[2][4];
#pragma unroll
    for (int ih = 0; ih < 2; ih++)
#pragma unroll
        for (int i = 0; i < 4; i++) {
            float s = 0.0f;
#pragma unroll
            for (int jh = 0; jh < 2; jh++)
#pragma unroll
                for (int j = 0; j < 4; j++)
                    s = fmaf(fmaxf(acc[ih][jh][i][j], 0.0f), w3v[jh][j], s);
            psum[ih][i] = s;
        }

    // all 32 lanes of a warp share tp -> reduce across lanes (cols)
#pragma unroll
    for (int off = 16; off > 0; off >>= 1)
#pragma unroll
        for (int ih = 0; ih < 2; ih++)
#pragma unroll
            for (int i = 0; i < 4; i++)
                psum[ih][i] += __shfl_xor_sync(0xffffffffu, psum[ih][i], off);

    if (tc == 0) {
        float bias3 = b3[0];
#pragma unroll
        for (int ih = 0; ih < 2; ih++)
#pragma unroll
            for (int i = 0; i < 4; i++) {
                int p = ih * 32 + tp * 4 + i;   // pair in [0,64)
                int pa = p >> 3, pb = p & 7;
                out[(b * NN + n0 + pa) * NN + (m0 + pb)] = psum[ih][i] + bias3;
            }
    }
}

// ---------------------------------------------------------------------------
extern "C" void kernel_launch(void* const* d_in, const int* in_sizes, int n_in,
                              void* d_out, int out_size) {
    const float* PhiA = (const float*)d_in[0];
    const float* PhiB = (const float*)d_in[1];
    const float* W1   = (const float*)d_in[2];
    const float* b1   = (const float*)d_in[3];
    const float* W2   = (const float*)d_in[4];
    const float* b2   = (const float*)d_in[5];
    const float* W3   = (const float*)d_in[6];
    const float* b3   = (const float*)d_in[7];
    float* out = (float*)d_out;

    precompute_kernel<<<BATCH * NN, HH>>>(PhiA, PhiB, W1, b1);

    const int smem_bytes = (16384 + 8192 + 2 * 8 * 257) * sizeof(float); // ~114.8KB
    cudaFuncSetAttribute(pair_mlp_kernel,
                         cudaFuncAttributeMaxDynamicSharedMemorySize, smem_bytes);
    dim3 grid(NN / 8, NN / 8, BATCH);   // 64 x 64 x 2 = 8192 blocks
    pair_mlp_kernel<<<grid, 256, smem_bytes>>>(W2, b2, W3, b3, out);
}

// round 3
// speedup vs baseline: 3.1024x; 3.1024x over previous
#include <cuda_runtime.h>
#include <cstdint>

#define NN 512
#define DD 128
#define HH 256
#define BB 2

// smem float offsets
#define OFF_HA   0            // [16][256]
#define OFF_HB   4096         // [8][256]
#define OFF_AS   6144         // [128][36]
#define OFF_BS   10752        // [32][136]
#define OFF_B2   15104        // [256]
#define OFF_W3   15360        // [256]
#define OFF_RED  15616        // [128]
#define SMEM_F   15744        // 62976 bytes

__device__ float g_hA[BB * NN * HH];
__device__ float g_hB[BB * NN * HH];
__device__ float g_W2t[HH * HH];   // W2 pre-rounded to tf32 values

__device__ __forceinline__ float to_tf32(float x) {
    float y; asm("cvt.rna.tf32.f32 %0, %1;" : "=f"(y) : "f"(x)); return y;
}

// ---------------------------------------------------------------------------
__global__ __launch_bounds__(HH) void precompute_kernel(
    const float* __restrict__ PhiA, const float* __restrict__ PhiB,
    const float* __restrict__ W1, const float* __restrict__ b1) {
    int bn = blockIdx.x;
    int h = threadIdx.x;
    __shared__ float sA[DD], sB[DD];
    if (h < DD) sA[h] = PhiA[bn * DD + h];
    else        sB[h - DD] = PhiB[bn * DD + (h - DD)];
    __syncthreads();
    float accA = b1[h], accB = 0.0f;
#pragma unroll 8
    for (int d = 0; d < DD; d++) {
        accA = fmaf(sA[d], W1[d * HH + h], accA);
        accB = fmaf(sB[d], W1[(DD + d) * HH + h], accB);
    }
    g_hA[bn * HH + h] = accA;
    g_hB[bn * HH + h] = accB;
}

__global__ void prep_w2(const float* __restrict__ W2) {
    int i = blockIdx.x * blockDim.x + threadIdx.x;
    g_W2t[i] = to_tf32(W2[i]);
}

// ---------------------------------------------------------------------------
extern __shared__ float smem[];

__global__ __launch_bounds__(256, 2) void pair_mlp_mma(
    const float* __restrict__ b2, const float* __restrict__ W3,
    const float* __restrict__ b3, float* __restrict__ out) {
    float* hAs = smem + OFF_HA;
    float* hBs = smem + OFF_HB;
    float* As  = smem + OFF_AS;
    float* Bs  = smem + OFF_BS;
    float* b2s = smem + OFF_B2;
    float* w3s = smem + OFF_W3;
    float* red = smem + OFF_RED;

    const int t    = threadIdx.x;
    const int wid  = t >> 5;
    const int lane = t & 31;
    const int gid  = lane >> 2;
    const int tig  = lane & 3;
    const int wm   = wid & 3;
    const int wn   = wid >> 2;

    const int bb = blockIdx.z;
    const int n0 = blockIdx.y * 16;
    const int m0 = blockIdx.x * 8;

#pragma unroll
    for (int j = 0; j < 4; j++) {
        int i = t + j * 256;
        int r = i >> 6, c4 = i & 63;
        ((float4*)hAs)[i] = ((const float4*)(g_hA + (size_t)(bb * NN + n0 + r) * HH))[c4];
        if (i < 512)
            ((float4*)hBs)[i] = ((const float4*)(g_hB + (size_t)(bb * NN + m0 + (i >> 6)) * HH))[c4];
    }
    b2s[t] = b2[t];
    w3s[t] = W3[t];
    if (t < 128) red[t] = 0.f;

    float acc[2][8][4];
    float psum[2][2] = {{0.f, 0.f}, {0.f, 0.f}};

    const float* Apt = As + (wm * 32 + gid) * 36 + tig;
    const float* Bpt = Bs + tig * 136 + wn * 64 + gid;

    for (int nh = 0; nh < 2; nh++) {
#pragma unroll
        for (int mt = 0; mt < 2; mt++)
#pragma unroll
            for (int nt = 0; nt < 8; nt++)
#pragma unroll
                for (int c = 0; c < 4; c++) acc[mt][nt][c] = 0.f;

        for (int ks = 0; ks < 8; ks++) {
            __syncthreads();
#pragma unroll
            for (int j = 0; j < 4; j++) {
                int i = t + j * 256;
                int m = i >> 3, f = i & 7;
                int a = m >> 3, bp = m & 7;
                int kc = ks * 32 + f * 4;
                float4 va = *(const float4*)&hAs[a * HH + kc];
                float4 vb = *(const float4*)&hBs[bp * HH + kc];
                float4 v;
                v.x = to_tf32(fmaxf(va.x + vb.x, 0.f));
                v.y = to_tf32(fmaxf(va.y + vb.y, 0.f));
                v.z = to_tf32(fmaxf(va.z + vb.z, 0.f));
                v.w = to_tf32(fmaxf(va.w + vb.w, 0.f));
                *(float4*)&As[m * 36 + f * 4] = v;
            }
#pragma unroll
            for (int j = 0; j < 4; j++) {
                int i = t + j * 256;
                int k = i >> 5, nf = i & 31;
                *(float4*)&Bs[k * 136 + nf * 4] =
                    *(const float4*)&g_W2t[(ks * 32 + k) * HH + nh * 128 + nf * 4];
            }
            __syncthreads();

#pragma unroll
            for (int k8 = 0; k8 < 4; k8++) {
                const int kk = k8 * 8;
                uint32_t afr[2][4];
#pragma unroll
                for (int mt = 0; mt < 2; mt++) {
                    afr[mt][0] = __float_as_uint(Apt[(mt * 16) * 36 + kk]);
                    afr[mt][1] = __float_as_uint(Apt[(mt * 16 + 8) * 36 + kk]);
                    afr[mt][2] = __float_as_uint(Apt[(mt * 16) * 36 + kk + 4]);
                    afr[mt][3] = __float_as_uint(Apt[(mt * 16 + 8) * 36 + kk + 4]);
                }
                uint32_t bfr[8][2];
#pragma unroll
                for (int nt = 0; nt < 8; nt++) {
                    bfr[nt][0] = __float_as_uint(Bpt[kk * 136 + nt * 8]);
                    bfr[nt][1] = __float_as_uint(Bpt[(kk + 4) * 136 + nt * 8]);
                }
#pragma unroll
                for (int mt = 0; mt < 2; mt++)
#pragma unroll
                    for (int nt = 0; nt < 8; nt++)
                        asm volatile(
                            "mma.sync.aligned.m16n8k8.row.col.f32.tf32.tf32.f32 "
                            "{%0,%1,%2,%3}, {%4,%5,%6,%7}, {%8,%9}, {%0,%1,%2,%3};"
                            : "+f"(acc[mt][nt][0]), "+f"(acc[mt][nt][1]),
                              "+f"(acc[mt][nt][2]), "+f"(acc[mt][nt][3])
                            : "r"(afr[mt][0]), "r"(afr[mt][1]),
                              "r"(afr[mt][2]), "r"(afr[mt][3]),
                              "r"(bfr[nt][0]), "r"(bfr[nt][1]));
            }
        }

#pragma unroll
        for (int mt = 0; mt < 2; mt++)
#pragma unroll
            for (int nt = 0; nt < 8; nt++) {
                int col = nh * 128 + wn * 64 + nt * 8 + tig * 2;
                float bq0 = b2s[col], bq1 = b2s[col + 1];
                float wq0 = w3s[col], wq1 = w3s[col + 1];
                psum[mt][0] = fmaf(fmaxf(acc[mt][nt][0] + bq0, 0.f), wq0, psum[mt][0]);
                psum[mt][0] = fmaf(fmaxf(acc[mt][nt][1] + bq1, 0.f), wq1, psum[mt][0]);
                psum[mt][1] = fmaf(fmaxf(acc[mt][nt][2] + bq0, 0.f), wq0, psum[mt][1]);
                psum[mt][1] = fmaf(fmaxf(acc[mt][nt][3] + bq1, 0.f), wq1, psum[mt][1]);
            }
    }

#pragma unroll
    for (int off = 1; off <= 2; off <<= 1)
#pragma unroll
        for (int mt = 0; mt < 2; mt++)
#pragma unroll
            for (int hi = 0; hi < 2; hi++)
                psum[mt][hi] += __shfl_xor_sync(0xffffffffu, psum[mt][hi], off);

    if (tig == 0) {
#pragma unroll
        for (int mt = 0; mt < 2; mt++)
#pragma unroll
            for (int hi = 0; hi < 2; hi++)
                atomicAdd(&red[wm * 32 + mt * 16 + hi * 8 + gid], psum[mt][hi]);
    }
    __syncthreads();
    if (t < 128) {
        int a = t >> 3, bp = t & 7;
        out[(size_t)(bb * NN + n0 + a) * NN + (m0 + bp)] = red[t] + b3[0];
    }
}

// ---------------------------------------------------------------------------
extern "C" void kernel_launch(void* const* d_in, const int* in_sizes, int n_in,
                              void* d_out, int out_size) {
    const float* PhiA = (const float*)d_in[0];
    const float* PhiB = (const float*)d_in[1];
    const float* W1   = (const float*)d_in[2];
    const float* b1   = (const float*)d_in[3];
    const float* W2   = (const float*)d_in[4];
    const float* b2   = (const float*)d_in[5];
    const float* W3   = (const float*)d_in[6];
    const float* b3   = (const float*)d_in[7];
    float* out = (float*)d_out;

    precompute_kernel<<<BB * NN, HH>>>(PhiA, PhiB, W1, b1);
    prep_w2<<<256, 256>>>(W2);

    const int smem_bytes = SMEM_F * 4;
    cudaFuncSetAttribute(pair_mlp_mma,
                         cudaFuncAttributeMaxDynamicSharedMemorySize, smem_bytes);
    dim3 grid(NN / 8, NN / 16, BB);   // 64 x 32 x 2 = 4096
    pair_mlp_mma<<<grid, 256, smem_bytes>>>(b2, W3, b3, out);
}

// round 5
// speedup vs baseline: 4.3133x; 1.3903x over previous
#include <cuda_runtime.h>
#include <cuda_fp16.h>
#include <cstdint>

#define NN 512
#define DD 128
#define HH 256
#define BB 2

// smem float offsets
#define OFF_HA   0            // [16][256] f32
#define OFF_HB   4096         // [8][256]  f32
#define OFF_AS   6144         // [128][20] b32 (half2 words, 16 valid + 4 pad)
#define OFF_BS   8704         // [128][20] b32
#define OFF_B2   11264        // [256]
#define OFF_W3   11520        // [256]
#define OFF_RED  11776        // [128]
#define SMEM_F   11904        // 47616 bytes

__device__ float  g_hA[BB * NN * HH];
__device__ float  g_hB[BB * NN * HH];
__device__ __half g_W2h[HH * HH];   // W2^T as fp16, [n][k] (k contiguous)

// ---------------------------------------------------------------------------
// hA = PhiA @ W1[:D] + b1 ; hB = PhiB @ W1[D:]   (4 rows per block: W1 reuse)
// ---------------------------------------------------------------------------
__global__ __launch_bounds__(HH) void precompute_kernel(
    const float* __restrict__ PhiA, const float* __restrict__ PhiB,
    const float* __restrict__ W1, const float* __restrict__ b1) {
    int bn0 = blockIdx.x * 4;
    int h = threadIdx.x;
    __shared__ float sA[4][DD], sB[4][DD];
#pragma unroll
    for (int j = 0; j < 2; j++) {
        int i = h + j * 256;          // 0..511
        int r = i >> 7, d = i & 127;
        sA[r][d] = PhiA[(bn0 + r) * DD + d];
        sB[r][d] = PhiB[(bn0 + r) * DD + d];
    }
    __syncthreads();
    float accA[4], accB[4];
    float bias = b1[h];
#pragma unroll
    for (int r = 0; r < 4; r++) { accA[r] = bias; accB[r] = 0.0f; }
#pragma unroll 4
    for (int d = 0; d < DD; d++) {
        float wa = W1[d * HH + h];
        float wb = W1[(DD + d) * HH + h];
#pragma unroll
        for (int r = 0; r < 4; r++) {
            accA[r] = fmaf(sA[r][d], wa, accA[r]);
            accB[r] = fmaf(sB[r][d], wb, accB[r]);
        }
    }
#pragma unroll
    for (int r = 0; r < 4; r++) {
        g_hA[(bn0 + r) * HH + h] = accA[r];
        g_hB[(bn0 + r) * HH + h] = accB[r];
    }
}

// W2^T fp16: g_W2h[n*256 + k] = fp16(W2[k][n])
__global__ void prep_w2(const float* __restrict__ W2) {
    int i = blockIdx.x * blockDim.x + threadIdx.x;   // 65536
    int n = i >> 8, k = i & 255;
    g_W2h[i] = __float2half_rn(W2[k * HH + n]);
}

// ---------------------------------------------------------------------------
// Pair MLP via fp16 m16n8k16 mma.sync. 256 thr (8 warps: wm 0..3, wn 0..1).
// 128 pairs (16 A x 8 B) x 256 cols, K=256 in 32-slabs, two 128-col halves.
// ---------------------------------------------------------------------------
extern __shared__ float smem[];

__global__ __launch_bounds__(256, 2) void pair_mlp_mma(
    const float* __restrict__ b2, const float* __restrict__ W3,
    const float* __restrict__ b3, float* __restrict__ out) {
    float* hAs = smem + OFF_HA;
    float* hBs = smem + OFF_HB;
    uint32_t* As32 = (uint32_t*)(smem + OFF_AS);
    uint32_t* Bs32 = (uint32_t*)(smem + OFF_BS);
    float* b2s = smem + OFF_B2;
    float* w3s = smem + OFF_W3;
    float* red = smem + OFF_RED;

    const int t    = threadIdx.x;
    const int wid  = t >> 5;
    const int lane = t & 31;
    const int gid  = lane >> 2;     // 0..7
    const int tig  = lane & 3;      // 0..3
    const int wm   = wid & 3;       // M quadrant (32 rows)
    const int wn   = wid >> 2;      // N half-of-half (64 cols)

    const int bb = blockIdx.z;
    const int n0 = blockIdx.y * 16;   // A rows
    const int m0 = blockIdx.x * 8;    // B rows

    // ---- stage hA (16x256), hB (8x256), b2, W3 ----
#pragma unroll
    for (int j = 0; j < 4; j++) {
        int i = t + j * 256;
        int r = i >> 6, c4 = i & 63;
        ((float4*)hAs)[i] = ((const float4*)(g_hA + (size_t)(bb * NN + n0 + r) * HH))[c4];
        if (i < 512)
            ((float4*)hBs)[i] = ((const float4*)(g_hB + (size_t)(bb * NN + m0 + (i >> 6)) * HH))[c4];
    }
    b2s[t] = b2[t];
    w3s[t] = W3[t];
    if (t < 128) red[t] = 0.f;

    float acc[2][8][4];
    float psum[2][2] = {{0.f, 0.f}, {0.f, 0.f}};

    const uint32_t* Apt = As32 + (wm * 32 + gid) * 20 + tig;
    const uint32_t* Bpt = Bs32 + (wn * 64 + gid) * 20 + tig;

    for (int nh = 0; nh < 2; nh++) {
#pragma unroll
        for (int mt = 0; mt < 2; mt++)
#pragma unroll
            for (int nt = 0; nt < 8; nt++)
#pragma unroll
                for (int c = 0; c < 4; c++) acc[mt][nt][c] = 0.f;

        for (int ks = 0; ks < 8; ks++) {
            __syncthreads();
            // ---- build A slab [128 m][16 words]: relu(hA+hB) -> fp16x2 ----
#pragma unroll
            for (int j = 0; j < 4; j++) {
                int i = t + j * 256;          // 0..1023 (word pairs)
                int m = i >> 3, wp = i & 7;   // wp = word-pair (4 k)
                int a = m >> 3, bp = m & 7;
                int kc = ks * 32 + wp * 4;
                float4 va = *(const float4*)&hAs[a * HH + kc];
                float4 vb = *(const float4*)&hBs[bp * HH + kc];
                __half2 h0 = __floats2half2_rn(fmaxf(va.x + vb.x, 0.f),
                                               fmaxf(va.y + vb.y, 0.f));
                __half2 h1 = __floats2half2_rn(fmaxf(va.z + vb.z, 0.f),
                                               fmaxf(va.w + vb.w, 0.f));
                uint2 wv = make_uint2(*(uint32_t*)&h0, *(uint32_t*)&h1);
                *(uint2*)&As32[m * 20 + wp * 2] = wv;
            }
            // ---- stage B slab [128 n][16 words] from g_W2h ----
#pragma unroll
            for (int j = 0; j < 2; j++) {
                int i = t + j * 256;          // 0..511 (uint4 = 4 words)
                int n = i >> 2, q = i & 3;
                const uint4* src = (const uint4*)g_W2h;
                // g_W2h word index: (nh*128+n)*128 + ks*16 + q*4  -> /4 for uint4
                uint4 v = src[((nh * 128 + n) * 128 + ks * 16 + q * 4) >> 2];
                *(uint4*)&Bs32[n * 20 + q * 4] = v;
            }
            __syncthreads();

#pragma unroll
            for (int kq = 0; kq < 2; kq++) {
                const int kw = kq * 8;
                uint32_t afr[2][4];
#pragma unroll
                for (int mt = 0; mt < 2; mt++) {
                    afr[mt][0] = Apt[(mt * 16) * 20 + kw];
                    afr[mt][1] = Apt[(mt * 16 + 8) * 20 + kw];
                    afr[mt][2] = Apt[(mt * 16) * 20 + kw + 4];
                    afr[mt][3] = Apt[(mt * 16 + 8) * 20 + kw + 4];
                }
                uint32_t bfr[8][2];
#pragma unroll
                for (int nt = 0; nt < 8; nt++) {
                    bfr[nt][0] = Bpt[nt * 160 + kw];
                    bfr[nt][1] = Bpt[nt * 160 + kw + 4];
                }
#pragma unroll
                for (int mt = 0; mt < 2; mt++)
#pragma unroll
                    for (int nt = 0; nt < 8; nt++)
                        asm volatile(
                            "mma.sync.aligned.m16n8k16.row.col.f32.f16.f16.f32 "
                            "{%0,%1,%2,%3}, {%4,%5,%6,%7}, {%8,%9}, {%0,%1,%2,%3};"
                            : "+f"(acc[mt][nt][0]), "+f"(acc[mt][nt][1]),
                              "+f"(acc[mt][nt][2]), "+f"(acc[mt][nt][3])
                            : "r"(afr[mt][0]), "r"(afr[mt][1]),
                              "r"(afr[mt][2]), "r"(afr[mt][3]),
                              "r"(bfr[nt][0]), "r"(bfr[nt][1]));
            }
        }

        // ---- fold this N-half: relu(acc+b2) . W3 ----
#pragma unroll
        for (int mt = 0; mt < 2; mt++)
#pragma unroll
            for (int nt = 0; nt < 8; nt++) {
                int col = nh * 128 + wn * 64 + nt * 8 + tig * 2;
                float bq0 = b2s[col], bq1 = b2s[col + 1];
                float wq0 = w3s[col], wq1 = w3s[col + 1];
                psum[mt][0] = fmaf(fmaxf(acc[mt][nt][0] + bq0, 0.f), wq0, psum[mt][0]);
                psum[mt][0] = fmaf(fmaxf(acc[mt][nt][1] + bq1, 0.f), wq1, psum[mt][0]);
                psum[mt][1] = fmaf(fmaxf(acc[mt][nt][2] + bq0, 0.f), wq0, psum[mt][1]);
                psum[mt][1] = fmaf(fmaxf(acc[mt][nt][3] + bq1, 0.f), wq1, psum[mt][1]);
            }
    }

    // reduce over tig lanes (cols within an 8-col group)
#pragma unroll
    for (int off = 1; off <= 2; off <<= 1)
#pragma unroll
        for (int mt = 0; mt < 2; mt++)
#pragma unroll
            for (int hi = 0; hi < 2; hi++)
                psum[mt][hi] += __shfl_xor_sync(0xffffffffu, psum[mt][hi], off);

    if (tig == 0) {
#pragma unroll
        for (int mt = 0; mt < 2; mt++)
#pragma unroll
            for (int hi = 0; hi < 2; hi++)
                atomicAdd(&red[wm * 32 + mt * 16 + hi * 8 + gid], psum[mt][hi]);
    }
    __syncthreads();
    if (t < 128) {
        int a = t >> 3, bp = t & 7;
        out[(size_t)(bb * NN + n0 + a) * NN + (m0 + bp)] = red[t] + b3[0];
    }
}

// ---------------------------------------------------------------------------
extern "C" void kernel_launch(void* const* d_in, const int* in_sizes, int n_in,
                              void* d_out, int out_size) {
    const float* PhiA = (const float*)d_in[0];
    const float* PhiB = (const float*)d_in[1];
    const float* W1   = (const float*)d_in[2];
    const float* b1   = (const float*)d_in[3];
    const float* W2   = (const float*)d_in[4];
    const float* b2   = (const float*)d_in[5];
    const float* W3   = (const float*)d_in[6];
    const float* b3   = (const float*)d_in[7];
    float* out = (float*)d_out;

    precompute_kernel<<<BB * NN / 4, HH>>>(PhiA, PhiB, W1, b1);
    prep_w2<<<256, 256>>>(W2);

    const int smem_bytes = SMEM_F * 4;   // 47616
    cudaFuncSetAttribute(pair_mlp_mma,
                         cudaFuncAttributeMaxDynamicSharedMemorySize, smem_bytes);
    dim3 grid(NN / 8, NN / 16, BB);   // 64 x 32 x 2 = 4096
    pair_mlp_mma<<<grid, 256, smem_bytes>>>(b2, W3, b3, out);
}

// round 7
// speedup vs baseline: 4.3208x; 1.0017x over previous
#include <cuda_runtime.h>
#include <cuda_fp16.h>
#include <cstdint>

#define NN 512
#define DD 128
#define HH 256
#define BB 2

// smem float offsets (main kernel)
#define OFF_HA   0            // [16][256] f32
#define OFF_HB   4096         // [8][256]  f32
#define OFF_AS   6144         // [128][20] b32 (half2 words, 16 valid + 4 pad)
#define OFF_BS   8704         // [256][20] b32
#define OFF_B2   13824        // [256]
#define OFF_W3   14080        // [256]
#define OFF_RED  14336        // [128]
#define SMEM_F   14464        // 57856 bytes

__device__ float  g_hA[BB * NN * HH];
__device__ float  g_hB[BB * NN * HH];
__device__ __half g_W2h[HH * HH];   // W2^T fp16, [n][k] k-contiguous

__device__ __forceinline__ uint32_t smem_u32(const void* p) {
    return (uint32_t)__cvta_generic_to_shared(p);
}
__device__ __forceinline__ void ldmat_x4(uint32_t& r0, uint32_t& r1,
                                         uint32_t& r2, uint32_t& r3, uint32_t a) {
    asm volatile("ldmatrix.sync.aligned.m8n8.x4.shared.b16 {%0,%1,%2,%3}, [%4];"
                 : "=r"(r0), "=r"(r1), "=r"(r2), "=r"(r3) : "r"(a));
}
#define CP_ASYNC16(dst, src) \
    asm volatile("cp.async.cg.shared.global [%0], [%1], 16;" :: "r"(dst), "l"(src))
#define CP_COMMIT() asm volatile("cp.async.commit_group;" ::: "memory")
#define CP_WAIT0()  asm volatile("cp.async.wait_group 0;" ::: "memory")

// ---------------------------------------------------------------------------
// hA = PhiA @ W1[:D] + b1 ; hB = PhiB @ W1[D:]   (2 rows/block, 512 blocks)
// ---------------------------------------------------------------------------
__global__ __launch_bounds__(HH) void precompute_kernel(
    const float* __restrict__ PhiA, const float* __restrict__ PhiB,
    const float* __restrict__ W1, const float* __restrict__ b1) {
    int bn0 = blockIdx.x * 2;
    int h = threadIdx.x;
    __shared__ float sA[2][DD], sB[2][DD];
    {
        int r = h >> 7, d = h & 127;
        sA[r][d] = PhiA[(bn0 + r) * DD + d];
        sB[r][d] = PhiB[(bn0 + r) * DD + d];
    }
    __syncthreads();
    float bias = b1[h];
    float accA0 = bias, accA1 = bias, accB0 = 0.f, accB1 = 0.f;
#pragma unroll 8
    for (int d = 0; d < DD; d++) {
        float wa = W1[d * HH + h];
        float wb = W1[(DD + d) * HH + h];
        accA0 = fmaf(sA[0][d], wa, accA0);
        accA1 = fmaf(sA[1][d], wa, accA1);
        accB0 = fmaf(sB[0][d], wb, accB0);
        accB1 = fmaf(sB[1][d], wb, accB1);
    }
    g_hA[bn0 * HH + h] = accA0;
    g_hA[(bn0 + 1) * HH + h] = accA1;
    g_hB[bn0 * HH + h] = accB0;
    g_hB[(bn0 + 1) * HH + h] = accB1;
}

// W2^T fp16: g_W2h[n*256 + k] = fp16(W2[k][n])
__global__ void prep_w2(const float* __restrict__ W2) {
    int i = blockIdx.x * blockDim.x + threadIdx.x;
    int n = i >> 8, k = i & 255;
    g_W2h[i] = __float2half_rn(W2[k * HH + n]);
}

// ---------------------------------------------------------------------------
// Pair MLP, fp16 m16n8k16. 512 thr, 16 warps: wm 0..3 (M 32-rows), wn 0..3
// (N 64-cols). 128 pairs (16 A x 8 B) x 256 cols, K=256 in 8 slabs of 32.
// ---------------------------------------------------------------------------
extern __shared__ float smem[];

__global__ __launch_bounds__(512, 1) void pair_mlp_mma(
    const float* __restrict__ b2, const float* __restrict__ W3,
    const float* __restrict__ b3, float* __restrict__ out) {
    float* hAs = smem + OFF_HA;
    float* hBs = smem + OFF_HB;
    uint32_t* As32 = (uint32_t*)(smem + OFF_AS);
    uint32_t* Bs32 = (uint32_t*)(smem + OFF_BS);
    float* b2s = smem + OFF_B2;
    float* w3s = smem + OFF_W3;
    float* red = smem + OFF_RED;

    const int t    = threadIdx.x;
    const int wid  = t >> 5;
    const int lane = t & 31;
    const int gid  = lane >> 2;
    const int tig  = lane & 3;
    const int wm   = wid & 3;       // M quadrant
    const int wn   = wid >> 2;      // N quarter (64 cols)

    const int bb = blockIdx.z;
    const int n0 = blockIdx.y * 16;
    const int m0 = blockIdx.x * 8;

    // ---- stage hA (16x256), hB (8x256), b2, W3 ----
#pragma unroll
    for (int j = 0; j < 2; j++) {
        int i = t + j * 512;                 // 0..1023
        int r = i >> 6, c4 = i & 63;
        ((float4*)hAs)[i] = ((const float4*)(g_hA + (size_t)(bb * NN + n0 + r) * HH))[c4];
        if (i < 512)
            ((float4*)hBs)[i] = ((const float4*)(g_hB + (size_t)(bb * NN + m0 + (i >> 6)) * HH))[c4];
    }
    if (t < 256) { b2s[t] = b2[t]; w3s[t] = W3[t]; }
    if (t < 128) red[t] = 0.f;

    const uint32_t as_base = smem_u32(As32);
    const uint32_t bs_base = smem_u32(Bs32);
    // ldmatrix lane address bases (row = lane&15, k-half = lane>>4)
    const uint32_t a_l = as_base + ((wm * 32 + (lane & 15)) * 20 + (lane >> 4) * 4) * 4;
    const uint32_t b_l = bs_base + ((wn * 64 + (lane & 15)) * 20 + (lane >> 4) * 4) * 4;

    float acc[2][8][4];
#pragma unroll
    for (int mt = 0; mt < 2; mt++)
#pragma unroll
        for (int nt = 0; nt < 8; nt++)
#pragma unroll
            for (int c = 0; c < 4; c++) acc[mt][nt][c] = 0.f;

    for (int ks = 0; ks < 8; ks++) {
        __syncthreads();
        // ---- B slab [256 n][16 words] via cp.async (overlaps A build) ----
        // src byte offset = word index * 4 = n*512 + ks*64 + q*16 (16B aligned)
#pragma unroll
        for (int j = 0; j < 2; j++) {
            int i = t + j * 512;             // 0..1023 uint4
            int n = i >> 2, q = i & 3;
            CP_ASYNC16(bs_base + (uint32_t)(n * 20 + q * 4) * 4,
                       (const char*)g_W2h + ((size_t)n * 128 + ks * 16 + q * 4) * 4);
        }
        CP_COMMIT();
        // ---- build A slab [128 m][16 words]: relu(hA+hB) -> fp16x2 ----
#pragma unroll
        for (int j = 0; j < 2; j++) {
            int i = t + j * 512;             // 0..1023 word-pairs
            int m = i >> 3, wp = i & 7;
            int a = m >> 3, bp = m & 7;
            int kc = ks * 32 + wp * 4;
            float4 va = *(const float4*)&hAs[a * HH + kc];
            float4 vb = *(const float4*)&hBs[bp * HH + kc];
            __half2 h0 = __floats2half2_rn(fmaxf(va.x + vb.x, 0.f),
                                           fmaxf(va.y + vb.y, 0.f));
            __half2 h1 = __floats2half2_rn(fmaxf(va.z + vb.z, 0.f),
                                           fmaxf(va.w + vb.w, 0.f));
            uint2 wv = make_uint2(*(uint32_t*)&h0, *(uint32_t*)&h1);
            *(uint2*)&As32[m * 20 + wp * 2] = wv;
        }
        CP_WAIT0();
        __syncthreads();

#pragma unroll
        for (int kq = 0; kq < 2; kq++) {
            const uint32_t koff = (uint32_t)(kq * 8 * 4);
            uint32_t afr[2][4];
#pragma unroll
            for (int mt = 0; mt < 2; mt++)
                ldmat_x4(afr[mt][0], afr[mt][1], afr[mt][2], afr[mt][3],
                         a_l + (uint32_t)(mt * 16 * 20 * 4) + koff);
            uint32_t bfr[8][2];
#pragma unroll
            for (int np = 0; np < 4; np++) {
                uint32_t r0, r1, r2, r3;
                ldmat_x4(r0, r1, r2, r3, b_l + (uint32_t)(np * 16 * 20 * 4) + koff);
                bfr[np * 2][0] = r0;     bfr[np * 2][1] = r2;
                bfr[np * 2 + 1][0] = r1; bfr[np * 2 + 1][1] = r3;
            }
#pragma unroll
            for (int mt = 0; mt < 2; mt++)
#pragma unroll
                for (int nt = 0; nt < 8; nt++)
                    asm volatile(
                        "mma.sync.aligned.m16n8k16.row.col.f32.f16.f16.f32 "
                        "{%0,%1,%2,%3}, {%4,%5,%6,%7}, {%8,%9}, {%0,%1,%2,%3};"
                        : "+f"(acc[mt][nt][0]), "+f"(acc[mt][nt][1]),
                          "+f"(acc[mt][nt][2]), "+f"(acc[mt][nt][3])
                        : "r"(afr[mt][0]), "r"(afr[mt][1]),
                          "r"(afr[mt][2]), "r"(afr[mt][3]),
                          "r"(bfr[nt][0]), "r"(bfr[nt][1]));
        }
    }

    // ---- epilogue: relu(acc+b2) . W3, reduce ----
    float psum[2][2] = {{0.f, 0.f}, {0.f, 0.f}};
#pragma unroll
    for (int mt = 0; mt < 2; mt++)
#pragma unroll
        for (int nt = 0; nt < 8; nt++) {
            int col = wn * 64 + nt * 8 + tig * 2;
            float bq0 = b2s[col], bq1 = b2s[col + 1];
            float wq0 = w3s[col], wq1 = w3s[col + 1];
            psum[mt][0] = fmaf(fmaxf(acc[mt][nt][0] + bq0, 0.f), wq0, psum[mt][0]);
            psum[mt][0] = fmaf(fmaxf(acc[mt][nt][1] + bq1, 0.f), wq1, psum[mt][0]);
            psum[mt][1] = fmaf(fmaxf(acc[mt][nt][2] + bq0, 0.f), wq0, psum[mt][1]);
            psum[mt][1] = fmaf(fmaxf(acc[mt][nt][3] + bq1, 0.f), wq1, psum[mt][1]);
        }

#pragma unroll
    for (int off = 1; off <= 2; off <<= 1)
#pragma unroll
        for (int mt = 0; mt < 2; mt++)
#pragma unroll
            for (int hi = 0; hi < 2; hi++)
                psum[mt][hi] += __shfl_xor_sync(0xffffffffu, psum[mt][hi], off);

    if (tig == 0) {
#pragma unroll
        for (int mt = 0; mt < 2; mt++)
#pragma unroll
            for (int hi = 0; hi < 2; hi++)
                atomicAdd(&red[wm * 32 + mt * 16 + hi * 8 + gid], psum[mt][hi]);
    }
    __syncthreads();
    if (t < 128) {
        int a = t >> 3, bp = t & 7;
        out[(size_t)(bb * NN + n0 + a) * NN + (m0 + bp)] = red[t] + b3[0];
    }
}

// ---------------------------------------------------------------------------
extern "C" void kernel_launch(void* const* d_in, const int* in_sizes, int n_in,
                              void* d_out, int out_size) {
    const float* PhiA = (const float*)d_in[0];
    const float* PhiB = (const float*)d_in[1];
    const float* W1   = (const float*)d_in[2];
    const float* b1   = (const float*)d_in[3];
    const float* W2   = (const float*)d_in[4];
    const float* b2   = (const float*)d_in[5];
    const float* W3   = (const float*)d_in[6];
    const float* b3   = (const float*)d_in[7];
    float* out = (float*)d_out;

    precompute_kernel<<<BB * NN / 2, HH>>>(PhiA, PhiB, W1, b1);
    prep_w2<<<256, 256>>>(W2);

    const int smem_bytes = SMEM_F * 4;   // 57856
    cudaFuncSetAttribute(pair_mlp_mma,
                         cudaFuncAttributeMaxDynamicSharedMemorySize, smem_bytes);
    dim3 grid(NN / 8, NN / 16, BB);   // 64 x 32 x 2 = 4096
    pair_mlp_mma<<<grid, 512, smem_bytes>>>(b2, W3, b3, out);
}

// round 8
// speedup vs baseline: 4.6312x; 1.0718x over previous
#include <cuda_runtime.h>
#include <cuda_fp16.h>
#include <cstdint>

#define NN 512
#define DD 128
#define HH 256
#define BB 2

// smem float offsets (main kernel)
#define OFF_HA   0            // [16][256] f32
#define OFF_HB   4096         // [8][256]  f32
#define OFF_AS0  6144         // [128][20] b32
#define OFF_AS1  8704         // [128][20] b32
#define OFF_BS0  11264        // [256][20] b32
#define OFF_BS1  16384        // [256][20] b32
#define OFF_B2   21504        // [256]
#define OFF_W3   21760        // [256]
#define OFF_RED  22016        // [128]
#define SMEM_F   22144        // 88576 bytes

#define A_STRIDE_B 10240u     // 2560 floats
#define B_STRIDE_B 20480u     // 5120 floats

__device__ float  g_hA[BB * NN * HH];
__device__ float  g_hB[BB * NN * HH];
__device__ __half g_W2h[HH * HH];   // W2^T fp16, [n][k] k-contiguous

__device__ __forceinline__ uint32_t smem_u32(const void* p) {
    return (uint32_t)__cvta_generic_to_shared(p);
}
__device__ __forceinline__ void ldmat_x4(uint32_t& r0, uint32_t& r1,
                                         uint32_t& r2, uint32_t& r3, uint32_t a) {
    asm volatile("ldmatrix.sync.aligned.m8n8.x4.shared.b16 {%0,%1,%2,%3}, [%4];"
                 : "=r"(r0), "=r"(r1), "=r"(r2), "=r"(r3) : "r"(a));
}
#define CP_ASYNC16(dst, src) \
    asm volatile("cp.async.cg.shared.global [%0], [%1], 16;" :: "r"(dst), "l"(src))
#define CP_COMMIT() asm volatile("cp.async.commit_group;" ::: "memory")
#define CP_WAIT0()  asm volatile("cp.async.wait_group 0;" ::: "memory")

// ---------------------------------------------------------------------------
// hA = PhiA @ W1[:D] + b1 ; hB = PhiB @ W1[D:]   (2 rows/block, 512 blocks)
// ---------------------------------------------------------------------------
__global__ __launch_bounds__(HH) void precompute_kernel(
    const float* __restrict__ PhiA, const float* __restrict__ PhiB,
    const float* __restrict__ W1, const float* __restrict__ b1) {
    int bn0 = blockIdx.x * 2;
    int h = threadIdx.x;
    __shared__ float sA[2][DD], sB[2][DD];
    {
        int r = h >> 7, d = h & 127;
        sA[r][d] = PhiA[(bn0 + r) * DD + d];
        sB[r][d] = PhiB[(bn0 + r) * DD + d];
    }
    __syncthreads();
    float bias = b1[h];
    float accA0 = bias, accA1 = bias, accB0 = 0.f, accB1 = 0.f;
#pragma unroll 8
    for (int d = 0; d < DD; d++) {
        float wa = W1[d * HH + h];
        float wb = W1[(DD + d) * HH + h];
        accA0 = fmaf(sA[0][d], wa, accA0);
        accA1 = fmaf(sA[1][d], wa, accA1);
        accB0 = fmaf(sB[0][d], wb, accB0);
        accB1 = fmaf(sB[1][d], wb, accB1);
    }
    g_hA[bn0 * HH + h] = accA0;
    g_hA[(bn0 + 1) * HH + h] = accA1;
    g_hB[bn0 * HH + h] = accB0;
    g_hB[(bn0 + 1) * HH + h] = accB1;
}

// W2^T fp16: g_W2h[n*256 + k] = fp16(W2[k][n])
__global__ void prep_w2(const float* __restrict__ W2) {
    int i = blockIdx.x * blockDim.x + threadIdx.x;
    int n = i >> 8, k = i & 255;
    g_W2h[i] = __float2half_rn(W2[k * HH + n]);
}

// ---------------------------------------------------------------------------
// Pair MLP, fp16 m16n8k16, double-buffered pipeline (1 sync/slab).
// 512 thr, 16 warps: wm 0..3 (M 32-rows), wn 0..3 (N 64-cols).
// 128 pairs (16 A x 8 B) x 256 cols, K=256 in 8 slabs of 32.
// ---------------------------------------------------------------------------
extern __shared__ float smem[];

__device__ __forceinline__ void build_A_slab(uint32_t* As32, const float* hAs,
                                             const float* hBs, int t, int ks) {
#pragma unroll
    for (int j = 0; j < 2; j++) {
        int i = t + j * 512;             // 0..1023 word-pairs
        int m = i >> 3, wp = i & 7;
        int a = m >> 3, bp = m & 7;
        int kc = ks * 32 + wp * 4;
        float4 va = *(const float4*)&hAs[a * HH + kc];
        float4 vb = *(const float4*)&hBs[bp * HH + kc];
        __half2 h0 = __floats2half2_rn(fmaxf(va.x + vb.x, 0.f),
                                       fmaxf(va.y + vb.y, 0.f));
        __half2 h1 = __floats2half2_rn(fmaxf(va.z + vb.z, 0.f),
                                       fmaxf(va.w + vb.w, 0.f));
        uint2 wv = make_uint2(*(uint32_t*)&h0, *(uint32_t*)&h1);
        *(uint2*)&As32[m * 20 + wp * 2] = wv;
    }
}

__device__ __forceinline__ void issue_B_slab(uint32_t bs_dst, int t, int ks) {
#pragma unroll
    for (int j = 0; j < 2; j++) {
        int i = t + j * 512;             // 0..1023 uint4
        int n = i >> 2, q = i & 3;
        CP_ASYNC16(bs_dst + (uint32_t)(n * 20 + q * 4) * 4,
                   (const char*)g_W2h + ((size_t)n * 128 + ks * 16 + q * 4) * 4);
    }
    CP_COMMIT();
}

__global__ __launch_bounds__(512, 1) void pair_mlp_mma(
    const float* __restrict__ b2, const float* __restrict__ W3,
    const float* __restrict__ b3, float* __restrict__ out) {
    float* hAs = smem + OFF_HA;
    float* hBs = smem + OFF_HB;
    uint32_t* As0 = (uint32_t*)(smem + OFF_AS0);
    uint32_t* As1 = (uint32_t*)(smem + OFF_AS1);
    float* b2s = smem + OFF_B2;
    float* w3s = smem + OFF_W3;
    float* red = smem + OFF_RED;

    const int t    = threadIdx.x;
    const int wid  = t >> 5;
    const int lane = t & 31;
    const int gid  = lane >> 2;
    const int tig  = lane & 3;
    const int wm   = wid & 3;
    const int wn   = wid >> 2;

    const int bb = blockIdx.z;
    const int n0 = blockIdx.y * 16;
    const int m0 = blockIdx.x * 8;

    // ---- stage hA (16x256), hB (8x256), b2, W3 ----
#pragma unroll
    for (int j = 0; j < 2; j++) {
        int i = t + j * 512;
        int r = i >> 6, c4 = i & 63;
        ((float4*)hAs)[i] = ((const float4*)(g_hA + (size_t)(bb * NN + n0 + r) * HH))[c4];
        if (i < 512)
            ((float4*)hBs)[i] = ((const float4*)(g_hB + (size_t)(bb * NN + m0 + (i >> 6)) * HH))[c4];
    }
    if (t < 256) { b2s[t] = b2[t]; w3s[t] = W3[t]; }
    if (t < 128) red[t] = 0.f;

    const uint32_t as_base = smem_u32((void*)(smem + OFF_AS0));
    const uint32_t bs_base = smem_u32((void*)(smem + OFF_BS0));
    const uint32_t a_l = as_base + ((wm * 32 + (lane & 15)) * 20 + (lane >> 4) * 4) * 4;
    const uint32_t b_l = bs_base + ((wn * 64 + (lane & 15)) * 20 + (lane >> 4) * 4) * 4;

    float acc[2][8][4];
#pragma unroll
    for (int mt = 0; mt < 2; mt++)
#pragma unroll
        for (int nt = 0; nt < 8; nt++)
#pragma unroll
            for (int c = 0; c < 4; c++) acc[mt][nt][c] = 0.f;

    __syncthreads();            // hAs/hBs ready

    // ---- prologue: fill buffer 0 ----
    issue_B_slab(bs_base, t, 0);
    build_A_slab(As0, hAs, hBs, t, 0);
    CP_WAIT0();
    __syncthreads();            // buf0 ready

    for (int ks = 0; ks < 8; ks++) {
        const uint32_t s = (uint32_t)(ks & 1);
        const uint32_t ns = s ^ 1u;

        // 1) kick next B load into the alternate buffer
        if (ks < 7) issue_B_slab(bs_base + ns * B_STRIDE_B, t, ks + 1);

        // 2) MMAs on buffer s (tensor pipe fills while we build next slab)
        const uint32_t a_ls = a_l + s * A_STRIDE_B;
        const uint32_t b_ls = b_l + s * B_STRIDE_B;
#pragma unroll
        for (int kq = 0; kq < 2; kq++) {
            const uint32_t koff = (uint32_t)(kq * 8 * 4);
            uint32_t afr[2][4];
#pragma unroll
            for (int mt = 0; mt < 2; mt++)
                ldmat_x4(afr[mt][0], afr[mt][1], afr[mt][2], afr[mt][3],
                         a_ls + (uint32_t)(mt * 16 * 20 * 4) + koff);
            uint32_t bfr[8][2];
#pragma unroll
            for (int np = 0; np < 4; np++) {
                uint32_t r0, r1, r2, r3;
                ldmat_x4(r0, r1, r2, r3, b_ls + (uint32_t)(np * 16 * 20 * 4) + koff);
                bfr[np * 2][0] = r0;     bfr[np * 2][1] = r2;
                bfr[np * 2 + 1][0] = r1; bfr[np * 2 + 1][1] = r3;
            }
#pragma unroll
            for (int mt = 0; mt < 2; mt++)
#pragma unroll
                for (int nt = 0; nt < 8; nt++)
                    asm volatile(
                        "mma.sync.aligned.m16n8k16.row.col.f32.f16.f16.f32 "
                        "{%0,%1,%2,%3}, {%4,%5,%6,%7}, {%8,%9}, {%0,%1,%2,%3};"
                        : "+f"(acc[mt][nt][0]), "+f"(acc[mt][nt][1]),
                          "+f"(acc[mt][nt][2]), "+f"(acc[mt][nt][3])
                        : "r"(afr[mt][0]), "r"(afr[mt][1]),
                          "r"(afr[mt][2]), "r"(afr[mt][3]),
                          "r"(bfr[nt][0]), "r"(bfr[nt][1]));
        }

        // 3) build next A slab into the alternate buffer (overlaps MMA drain)
        if (ks < 7) {
            build_A_slab(s ? As0 : As1, hAs, hBs, t, ks + 1);
            CP_WAIT0();
        }
        __syncthreads();
    }

    // ---- epilogue: relu(acc+b2) . W3, reduce ----
    float psum[2][2] = {{0.f, 0.f}, {0.f, 0.f}};
#pragma unroll
    for (int mt = 0; mt < 2; mt++)
#pragma unroll
        for (int nt = 0; nt < 8; nt++) {
            int col = wn * 64 + nt * 8 + tig * 2;
            float bq0 = b2s[col], bq1 = b2s[col + 1];
            float wq0 = w3s[col], wq1 = w3s[col + 1];
            psum[mt][0] = fmaf(fmaxf(acc[mt][nt][0] + bq0, 0.f), wq0, psum[mt][0]);
            psum[mt][0] = fmaf(fmaxf(acc[mt][nt][1] + bq1, 0.f), wq1, psum[mt][0]);
            psum[mt][1] = fmaf(fmaxf(acc[mt][nt][2] + bq0, 0.f), wq0, psum[mt][1]);
            psum[mt][1] = fmaf(fmaxf(acc[mt][nt][3] + bq1, 0.f), wq1, psum[mt][1]);
        }

#pragma unroll
    for (int off = 1; off <= 2; off <<= 1)
#pragma unroll
        for (int mt = 0; mt < 2; mt++)
#pragma unroll
            for (int hi = 0; hi < 2; hi++)
                psum[mt][hi] += __shfl_xor_sync(0xffffffffu, psum[mt][hi], off);

    if (tig == 0) {
#pragma unroll
        for (int mt = 0; mt < 2; mt++)
#pragma unroll
            for (int hi = 0; hi < 2; hi++)
                atomicAdd(&red[wm * 32 + mt * 16 + hi * 8 + gid], psum[mt][hi]);
    }
    __syncthreads();
    if (t < 128) {
        int a = t >> 3, bp = t & 7;
        out[(size_t)(bb * NN + n0 + a) * NN + (m0 + bp)] = red[t] + b3[0];
    }
}

// ---------------------------------------------------------------------------
extern "C" void kernel_launch(void* const* d_in, const int* in_sizes, int n_in,
                              void* d_out, int out_size) {
    const float* PhiA = (const float*)d_in[0];
    const float* PhiB = (const float*)d_in[1];
    const float* W1   = (const float*)d_in[2];
    const float* b1   = (const float*)d_in[3];
    const float* W2   = (const float*)d_in[4];
    const float* b2   = (const float*)d_in[5];
    const float* W3   = (const float*)d_in[6];
    const float* b3   = (const float*)d_in[7];
    float* out = (float*)d_out;

    precompute_kernel<<<BB * NN / 2, HH>>>(PhiA, PhiB, W1, b1);
    prep_w2<<<256, 256>>>(W2);

    const int smem_bytes = SMEM_F * 4;   // 88576
    cudaFuncSetAttribute(pair_mlp_mma,
                         cudaFuncAttributeMaxDynamicSharedMemorySize, smem_bytes);
    dim3 grid(NN / 8, NN / 16, BB);   // 64 x 32 x 2 = 4096
    pair_mlp_mma<<<grid, 512, smem_bytes>>>(b2, W3, b3, out);
}

// round 9
// speedup vs baseline: 4.6702x; 1.0084x over previous
#include <cuda_runtime.h>
#include <cuda_fp16.h>
#include <cstdint>

#define NN 512
#define DD 128
#define HH 256
#define BB 2

// smem float offsets (main kernel)
#define OFF_HA   0            // [16][256] f32
#define OFF_HB   4096         // [8][256]  f32
#define OFF_AS0  6144         // [128][20] b32
#define OFF_AS1  8704         // [128][20] b32
#define OFF_BS0  11264        // [256][20] b32
#define OFF_BS1  16384        // [256][20] b32
#define OFF_B2   21504        // [256]
#define OFF_W3   21760        // [256]
#define OFF_RED  22016        // [128]
#define SMEM_F   22144        // 88576 bytes

#define A_STRIDE_B 10240u
#define B_STRIDE_B 20480u

__device__ float  g_hA[BB * NN * HH];
__device__ float  g_hB[BB * NN * HH];
__device__ __half g_W2h[HH * HH];   // W2^T fp16, [n][k] k-contiguous

__device__ __forceinline__ uint32_t smem_u32(const void* p) {
    return (uint32_t)__cvta_generic_to_shared(p);
}
__device__ __forceinline__ void ldmat_x4(uint32_t& r0, uint32_t& r1,
                                         uint32_t& r2, uint32_t& r3, uint32_t a) {
    asm volatile("ldmatrix.sync.aligned.m8n8.x4.shared.b16 {%0,%1,%2,%3}, [%4];"
                 : "=r"(r0), "=r"(r1), "=r"(r2), "=r"(r3) : "r"(a));
}
#define CP_ASYNC16(dst, src) \
    asm volatile("cp.async.cg.shared.global [%0], [%1], 16;" :: "r"(dst), "l"(src))
#define CP_COMMIT() asm volatile("cp.async.commit_group;" ::: "memory")
#define CP_WAIT0()  asm volatile("cp.async.wait_group 0;" ::: "memory")

// ---------------------------------------------------------------------------
// Fused prep: blocks 0..127 -> hA/hB (8 rows each); blocks 128..191 -> W2^T.
// hA = PhiA @ W1[:D] + b1 ; hB = PhiB @ W1[D:]
// ---------------------------------------------------------------------------
__global__ __launch_bounds__(256) void prep_kernel(
    const float* __restrict__ PhiA, const float* __restrict__ PhiB,
    const float* __restrict__ W1, const float* __restrict__ b1,
    const float* __restrict__ W2) {
    const int t = threadIdx.x;
    if (blockIdx.x >= BB * NN / 8) {
        // ---- W2^T fp16: g_W2h[n*256+k] = fp16(W2[k][n]) ----
        int base = (blockIdx.x - BB * NN / 8) * 1024 + t * 4;
#pragma unroll
        for (int j = 0; j < 4; j++) {
            int i = base + j;
            int n = i >> 8, k = i & 255;
            g_W2h[i] = __float2half_rn(W2[k * HH + n]);
        }
        return;
    }
    const int bn0 = blockIdx.x * 8;
    const int h = t;
    __shared__ float sAT[DD][8], sBT[DD][8];   // transposed: [d][r]
#pragma unroll
    for (int j = 0; j < 4; j++) {
        int i = t + j * 256;          // 0..1023
        int r = i >> 7, d = i & 127;
        sAT[d][r] = PhiA[(bn0 + r) * DD + d];
        sBT[d][r] = PhiB[(bn0 + r) * DD + d];
    }
    __syncthreads();
    float bias = b1[h];
    float accA[8], accB[8];
#pragma unroll
    for (int r = 0; r < 8; r++) { accA[r] = bias; accB[r] = 0.f; }
#pragma unroll 4
    for (int d = 0; d < DD; d++) {
        float wa = W1[d * HH + h];
        float wb = W1[(DD + d) * HH + h];
        float4 a0 = *(const float4*)&sAT[d][0];
        float4 a1 = *(const float4*)&sAT[d][4];
        float4 b0 = *(const float4*)&sBT[d][0];
        float4 b1v = *(const float4*)&sBT[d][4];
        accA[0] = fmaf(a0.x, wa, accA[0]); accA[1] = fmaf(a0.y, wa, accA[1]);
        accA[2] = fmaf(a0.z, wa, accA[2]); accA[3] = fmaf(a0.w, wa, accA[3]);
        accA[4] = fmaf(a1.x, wa, accA[4]); accA[5] = fmaf(a1.y, wa, accA[5]);
        accA[6] = fmaf(a1.z, wa, accA[6]); accA[7] = fmaf(a1.w, wa, accA[7]);
        accB[0] = fmaf(b0.x, wb, accB[0]); accB[1] = fmaf(b0.y, wb, accB[1]);
        accB[2] = fmaf(b0.z, wb, accB[2]); accB[3] = fmaf(b0.w, wb, accB[3]);
        accB[4] = fmaf(b1v.x, wb, accB[4]); accB[5] = fmaf(b1v.y, wb, accB[5]);
        accB[6] = fmaf(b1v.z, wb, accB[6]); accB[7] = fmaf(b1v.w, wb, accB[7]);
    }
#pragma unroll
    for (int r = 0; r < 8; r++) {
        g_hA[(bn0 + r) * HH + h] = accA[r];
        g_hB[(bn0 + r) * HH + h] = accB[r];
    }
}

// ---------------------------------------------------------------------------
// Pair MLP, fp16 m16n8k16, double-buffered pipeline (1 sync/slab).
// ---------------------------------------------------------------------------
extern __shared__ float smem[];

__device__ __forceinline__ void build_A_slab(uint32_t* As32, const float* hAs,
                                             const float* hBs, int t, int ks) {
#pragma unroll
    for (int j = 0; j < 2; j++) {
        int i = t + j * 512;
        int m = i >> 3, wp = i & 7;
        int a = m >> 3, bp = m & 7;
        int kc = ks * 32 + wp * 4;
        float4 va = *(const float4*)&hAs[a * HH + kc];
        float4 vb = *(const float4*)&hBs[bp * HH + kc];
        __half2 h0 = __floats2half2_rn(fmaxf(va.x + vb.x, 0.f),
                                       fmaxf(va.y + vb.y, 0.f));
        __half2 h1 = __floats2half2_rn(fmaxf(va.z + vb.z, 0.f),
                                       fmaxf(va.w + vb.w, 0.f));
        uint2 wv = make_uint2(*(uint32_t*)&h0, *(uint32_t*)&h1);
        *(uint2*)&As32[m * 20 + wp * 2] = wv;
    }
}

__device__ __forceinline__ void issue_B_slab(uint32_t bs_dst, int t, int ks) {
#pragma unroll
    for (int j = 0; j < 2; j++) {
        int i = t + j * 512;
        int n = i >> 2, q = i & 3;
        CP_ASYNC16(bs_dst + (uint32_t)(n * 20 + q * 4) * 4,
                   (const char*)g_W2h + ((size_t)n * 128 + ks * 16 + q * 4) * 4);
    }
    CP_COMMIT();
}

__global__ __launch_bounds__(512, 1) void pair_mlp_mma(
    const float* __restrict__ b2, const float* __restrict__ W3,
    const float* __restrict__ b3, float* __restrict__ out) {
    float* hAs = smem + OFF_HA;
    float* hBs = smem + OFF_HB;
    uint32_t* As0 = (uint32_t*)(smem + OFF_AS0);
    uint32_t* As1 = (uint32_t*)(smem + OFF_AS1);
    float* b2s = smem + OFF_B2;
    float* w3s = smem + OFF_W3;
    float* red = smem + OFF_RED;

    const int t    = threadIdx.x;
    const int wid  = t >> 5;
    const int lane = t & 31;
    const int gid  = lane >> 2;
    const int tig  = lane & 3;
    const int wm   = wid & 3;
    const int wn   = wid >> 2;

    const int bb = blockIdx.z;
    const int n0 = blockIdx.y * 16;
    const int m0 = blockIdx.x * 8;

    const uint32_t as_base = smem_u32((void*)(smem + OFF_AS0));
    const uint32_t bs_base = smem_u32((void*)(smem + OFF_BS0));
    const uint32_t a_l = as_base + ((wm * 32 + (lane & 15)) * 20 + (lane >> 4) * 4) * 4;
    const uint32_t b_l = bs_base + ((wn * 64 + (lane & 15)) * 20 + (lane >> 4) * 4) * 4;

    // B slab 0 fetch rides under the staging LDG latency below
    issue_B_slab(bs_base, t, 0);

    // ---- stage hA (16x256), hB (8x256), b2, W3 ----
#pragma unroll
    for (int j = 0; j < 2; j++) {
        int i = t + j * 512;
        int r = i >> 6, c4 = i & 63;
        ((float4*)hAs)[i] = ((const float4*)(g_hA + (size_t)(bb * NN + n0 + r) * HH))[c4];
        if (i < 512)
            ((float4*)hBs)[i] = ((const float4*)(g_hB + (size_t)(bb * NN + m0 + (i >> 6)) * HH))[c4];
    }
    if (t < 256) { b2s[t] = b2[t]; w3s[t] = W3[t]; }
    if (t < 128) red[t] = 0.f;

    float acc[2][8][4];
#pragma unroll
    for (int mt = 0; mt < 2; mt++)
#pragma unroll
        for (int nt = 0; nt < 8; nt++)
#pragma unroll
            for (int c = 0; c < 4; c++) acc[mt][nt][c] = 0.f;

    __syncthreads();            // hAs/hBs ready

    build_A_slab(As0, hAs, hBs, t, 0);
    CP_WAIT0();
    __syncthreads();            // buf0 ready

    for (int ks = 0; ks < 8; ks++) {
        const uint32_t s = (uint32_t)(ks & 1);
        const uint32_t ns = s ^ 1u;

        if (ks < 7) issue_B_slab(bs_base + ns * B_STRIDE_B, t, ks + 1);

        const uint32_t a_ls = a_l + s * A_STRIDE_B;
        const uint32_t b_ls = b_l + s * B_STRIDE_B;
#pragma unroll
        for (int kq = 0; kq < 2; kq++) {
            const uint32_t koff = (uint32_t)(kq * 8 * 4);
            uint32_t afr[2][4];
#pragma unroll
            for (int mt = 0; mt < 2; mt++)
                ldmat_x4(afr[mt][0], afr[mt][1], afr[mt][2], afr[mt][3],
                         a_ls + (uint32_t)(mt * 16 * 20 * 4) + koff);
            uint32_t bfr[8][2];
#pragma unroll
            for (int np = 0; np < 4; np++) {
                uint32_t r0, r1, r2, r3;
                ldmat_x4(r0, r1, r2, r3, b_ls + (uint32_t)(np * 16 * 20 * 4) + koff);
                bfr[np * 2][0] = r0;     bfr[np * 2][1] = r2;
                bfr[np * 2 + 1][0] = r1; bfr[np * 2 + 1][1] = r3;
            }
#pragma unroll
            for (int mt = 0; mt < 2; mt++)
#pragma unroll
                for (int nt = 0; nt < 8; nt++)
                    asm volatile(
                        "mma.sync.aligned.m16n8k16.row.col.f32.f16.f16.f32 "
                        "{%0,%1,%2,%3}, {%4,%5,%6,%7}, {%8,%9}, {%0,%1,%2,%3};"
                        : "+f"(acc[mt][nt][0]), "+f"(acc[mt][nt][1]),
                          "+f"(acc[mt][nt][2]), "+f"(acc[mt][nt][3])
                        : "r"(afr[mt][0]), "r"(afr[mt][1]),
                          "r"(afr[mt][2]), "r"(afr[mt][3]),
                          "r"(bfr[nt][0]), "r"(bfr[nt][1]));
        }

        if (ks < 7) {
            build_A_slab(s ? As0 : As1, hAs, hBs, t, ks + 1);
            CP_WAIT0();
        }
        __syncthreads();
    }

    // ---- epilogue: relu(acc+b2) . W3, reduce ----
    float psum[2][2] = {{0.f, 0.f}, {0.f, 0.f}};
#pragma unroll
    for (int mt = 0; mt < 2; mt++)
#pragma unroll
        for (int nt = 0; nt < 8; nt++) {
            int col = wn * 64 + nt * 8 + tig * 2;
            float bq0 = b2s[col], bq1 = b2s[col + 1];
            float wq0 = w3s[col], wq1 = w3s[col + 1];
            psum[mt][0] = fmaf(fmaxf(acc[mt][nt][0] + bq0, 0.f), wq0, psum[mt][0]);
            psum[mt][0] = fmaf(fmaxf(acc[mt][nt][1] + bq1, 0.f), wq1, psum[mt][0]);
            psum[mt][1] = fmaf(fmaxf(acc[mt][nt][2] + bq0, 0.f), wq0, psum[mt][1]);
            psum[mt][1] = fmaf(fmaxf(acc[mt][nt][3] + bq1, 0.f), wq1, psum[mt][1]);
        }

#pragma unroll
    for (int off = 1; off <= 2; off <<= 1)
#pragma unroll
        for (int mt = 0; mt < 2; mt++)
#pragma unroll
            for (int hi = 0; hi < 2; hi++)
                psum[mt][hi] += __shfl_xor_sync(0xffffffffu, psum[mt][hi], off);

    if (tig == 0) {
#pragma unroll
        for (int mt = 0; mt < 2; mt++)
#pragma unroll
            for (int hi = 0; hi < 2; hi++)
                atomicAdd(&red[wm * 32 + mt * 16 + hi * 8 + gid], psum[mt][hi]);
    }
    __syncthreads();
    if (t < 128) {
        int a = t >> 3, bp = t & 7;
        out[(size_t)(bb * NN + n0 + a) * NN + (m0 + bp)] = red[t] + b3[0];
    }
}

// ---------------------------------------------------------------------------
extern "C" void kernel_launch(void* const* d_in, const int* in_sizes, int n_in,
                              void* d_out, int out_size) {
    const float* PhiA = (const float*)d_in[0];
    const float* PhiB = (const float*)d_in[1];
    const float* W1   = (const float*)d_in[2];
    const float* b1   = (const float*)d_in[3];
    const float* W2   = (const float*)d_in[4];
    const float* b2   = (const float*)d_in[5];
    const float* W3   = (const float*)d_in[6];
    const float* b3   = (const float*)d_in[7];
    float* out = (float*)d_out;

    prep_kernel<<<BB * NN / 8 + 64, 256>>>(PhiA, PhiB, W1, b1, W2);

    const int smem_bytes = SMEM_F * 4;   // 88576
    cudaFuncSetAttribute(pair_mlp_mma,
                         cudaFuncAttributeMaxDynamicSharedMemorySize, smem_bytes);
    dim3 grid(NN / 8, NN / 16, BB);   // 64 x 32 x 2 = 4096
    pair_mlp_mma<<<grid, 512, smem_bytes>>>(b2, W3, b3, out);
}